// round 3
// baseline (speedup 1.0000x reference)
#include <cuda_runtime.h>
#include <cuda_bf16.h>
#include <mma.h>
#include <cstdint>

using namespace nvcuda;

// ---------------------------------------------------------------------------
// MLPLinkPredictor: score[e] = W2 . relu(W1 [h[src];h[dst]] + b1) + b2
//
// Identity: W1 [h_s; h_d] = W1a h_s + W1b h_d  (split W1 columns).
// => Precompute node projections C[n, 0:256] = h[n] @ W1a.T
//                                C[n, 256:512] = h[n] @ W1b.T
//    (one GEMM: 50000 x 512 x 256 on tensor cores, 3xTF32 for fp32 accuracy),
//    then per edge a cheap gather + relu-dot.
// ---------------------------------------------------------------------------

#define N_NODES 50000
#define N_FEAT  256
#define N_OUT   512            // 2 * N_FEAT concatenated projections
#define N_NODES_PAD 50048      // padded to multiple of 128 so full wmma tiles can store

// Scratch (device globals: allocation-free per harness rules)
__device__ float g_C[(size_t)N_NODES_PAD * N_OUT];  // ~102.5 MB node projections
__device__ float g_Wt[(size_t)N_OUT * N_FEAT];      // 512 KB repacked weights

// ---------------------------------------------------------------------------
// Repack W1_w [256, 512] row-major into Wt [512, 256]:
//   Wt[j, k] = (j < 256) ? W1[j, k] : W1[j-256, 256 + k]
// ---------------------------------------------------------------------------
__global__ void repack_kernel(const float* __restrict__ W1) {
    int idx = blockIdx.x * blockDim.x + threadIdx.x;
    if (idx >= N_OUT * N_FEAT) return;
    int j = idx / N_FEAT;
    int k = idx % N_FEAT;
    float v = (j < N_FEAT) ? W1[j * (2 * N_FEAT) + k]
                           : W1[(j - N_FEAT) * (2 * N_FEAT) + N_FEAT + k];
    g_Wt[idx] = v;
}

// ---------------------------------------------------------------------------
// Tensor-core GEMM (3xTF32): g_C = h[50000,256] @ g_Wt[512,256]^T
// Block tile 128x64, BK=16. 8 warps: 4 along M (32 rows each), 2 along N
// (32 cols each). Per warp: 2x2 wmma (16x16) accumulator tiles.
// fp32 operand x = hi + lo with hi = tf32(x), lo = tf32(x - hi);
// D += ah*bh + al*bh + ah*bl  (al*bl term ~2^-24, dropped).
// ---------------------------------------------------------------------------
#define BM 128
#define BN 64
#define BK 16
#define PAD 4
#define LDS_A (BK + PAD)       // 20 floats per row

__global__ __launch_bounds__(256, 2)
void gemm_tc_kernel(const float* __restrict__ h) {
    __shared__ float As[BM][LDS_A];
    __shared__ float Bs[BN][LDS_A];

    const int tid = threadIdx.x;
    const int wid = tid >> 5;
    const int bn = blockIdx.x;          // 0..7   (512/64)
    const int bm = blockIdx.y;          // 0..390
    const int wm = (wid & 3) * 32;      // warp row offset in tile
    const int wn = (wid >> 2) * 32;     // warp col offset in tile

    wmma::fragment<wmma::accumulator, 16, 16, 8, float> acc[2][2];
#pragma unroll
    for (int i = 0; i < 2; i++)
#pragma unroll
        for (int j = 0; j < 2; j++) wmma::fill_fragment(acc[i][j], 0.0f);

    // global load indices: each thread owns one float4 column slot of a row
    const int lr = tid >> 2;            // 0..63
    const int lc = (tid & 3) * 4;       // 0,4,8,12

    for (int k0 = 0; k0 < N_FEAT; k0 += BK) {
        // --- stage A tile: 128 rows x 16 cols (two rows per thread) ---
#pragma unroll
        for (int rr = 0; rr < BM; rr += 64) {
            int row = lr + rr;
            int grow = bm * BM + row;
            float4 v = make_float4(0.f, 0.f, 0.f, 0.f);
            if (grow < N_NODES)
                v = *reinterpret_cast<const float4*>(&h[(size_t)grow * N_FEAT + k0 + lc]);
            As[row][lc + 0] = v.x;
            As[row][lc + 1] = v.y;
            As[row][lc + 2] = v.z;
            As[row][lc + 3] = v.w;
        }
        // --- stage B tile: 64 rows x 16 cols (one row per thread) ---
        {
            int grow = bn * BN + lr;    // always < 512
            float4 v = *reinterpret_cast<const float4*>(&g_Wt[(size_t)grow * N_FEAT + k0 + lc]);
            Bs[lr][lc + 0] = v.x;
            Bs[lr][lc + 1] = v.y;
            Bs[lr][lc + 2] = v.z;
            Bs[lr][lc + 3] = v.w;
        }
        __syncthreads();

#pragma unroll
        for (int ks = 0; ks < BK; ks += 8) {
            wmma::fragment<wmma::matrix_a, 16, 16, 8, wmma::precision::tf32, wmma::row_major> a_hi[2], a_lo[2];
            wmma::fragment<wmma::matrix_b, 16, 16, 8, wmma::precision::tf32, wmma::col_major> b_hi[2], b_lo[2];

#pragma unroll
            for (int i = 0; i < 2; i++) {
                wmma::fragment<wmma::matrix_a, 16, 16, 8, wmma::precision::tf32, wmma::row_major> af;
                wmma::load_matrix_sync(af, &As[wm + i * 16][ks], LDS_A);
#pragma unroll
                for (int t = 0; t < af.num_elements; t++) {
                    float v  = af.x[t];
                    float hi = wmma::__float_to_tf32(v);
                    a_hi[i].x[t] = hi;
                    a_lo[i].x[t] = wmma::__float_to_tf32(v - hi);
                }
            }
#pragma unroll
            for (int j = 0; j < 2; j++) {
                wmma::fragment<wmma::matrix_b, 16, 16, 8, wmma::precision::tf32, wmma::col_major> bf;
                wmma::load_matrix_sync(bf, &Bs[wn + j * 16][ks], LDS_A);
#pragma unroll
                for (int t = 0; t < bf.num_elements; t++) {
                    float v  = bf.x[t];
                    float hi = wmma::__float_to_tf32(v);
                    b_hi[j].x[t] = hi;
                    b_lo[j].x[t] = wmma::__float_to_tf32(v - hi);
                }
            }

#pragma unroll
            for (int i = 0; i < 2; i++)
#pragma unroll
                for (int j = 0; j < 2; j++) {
                    wmma::mma_sync(acc[i][j], a_lo[i], b_hi[j], acc[i][j]);
                    wmma::mma_sync(acc[i][j], a_hi[i], b_lo[j], acc[i][j]);
                    wmma::mma_sync(acc[i][j], a_hi[i], b_hi[j], acc[i][j]);
                }
        }
        __syncthreads();
    }

    // epilogue: rows are padded (g_C has N_NODES_PAD rows), so full-tile stores are safe
#pragma unroll
    for (int i = 0; i < 2; i++) {
#pragma unroll
        for (int j = 0; j < 2; j++) {
            int row = bm * BM + wm + i * 16;
            int col = bn * BN + wn + j * 16;
            wmma::store_matrix_sync(&g_C[(size_t)row * N_OUT + col], acc[i][j],
                                    N_OUT, wmma::mem_row_major);
        }
    }
}

// ---------------------------------------------------------------------------
// Edge kernel: one warp per edge.
//   hid[j] = relu(C[src, j] + C[dst, 256 + j] + b1[j]),  j in [0,256)
//   out[e] = dot(hid, W2) + b2
// ---------------------------------------------------------------------------
__global__ __launch_bounds__(256)
void edge_kernel(const int* __restrict__ src, const int* __restrict__ dst,
                 const float* __restrict__ b1, const float* __restrict__ W2w,
                 const float* __restrict__ W2b, float* __restrict__ out, int E) {
    int warp = (blockIdx.x * blockDim.x + threadIdx.x) >> 5;
    int lane = threadIdx.x & 31;
    if (warp >= E) return;

    int s = src[warp];
    int d = dst[warp];

    const float4* Cs = reinterpret_cast<const float4*>(g_C + (size_t)s * N_OUT);          // first 256
    const float4* Cd = reinterpret_cast<const float4*>(g_C + (size_t)d * N_OUT + N_FEAT); // second 256
    const float4* B1 = reinterpret_cast<const float4*>(b1);
    const float4* W2 = reinterpret_cast<const float4*>(W2w);

    float acc = 0.f;
#pragma unroll
    for (int p = 0; p < 2; p++) {
        int i = p * 32 + lane;
        float4 a  = Cs[i];
        float4 b  = Cd[i];
        float4 bb = B1[i];
        float4 w  = W2[i];
        float h0 = fmaxf(a.x + b.x + bb.x, 0.f);
        float h1 = fmaxf(a.y + b.y + bb.y, 0.f);
        float h2 = fmaxf(a.z + b.z + bb.z, 0.f);
        float h3 = fmaxf(a.w + b.w + bb.w, 0.f);
        acc = fmaf(h0, w.x, acc);
        acc = fmaf(h1, w.y, acc);
        acc = fmaf(h2, w.z, acc);
        acc = fmaf(h3, w.w, acc);
    }

#pragma unroll
    for (int off = 16; off; off >>= 1)
        acc += __shfl_down_sync(0xffffffffu, acc, off);

    if (lane == 0) out[warp] = acc + W2b[0];
}

// ---------------------------------------------------------------------------
extern "C" void kernel_launch(void* const* d_in, const int* in_sizes, int n_in,
                              void* d_out, int out_size) {
    const float* h    = (const float*)d_in[0];
    const int*   src  = (const int*)  d_in[1];
    const int*   dst  = (const int*)  d_in[2];
    const float* W1w  = (const float*)d_in[3];
    const float* W1b  = (const float*)d_in[4];
    const float* W2w  = (const float*)d_in[5];
    const float* W2b  = (const float*)d_in[6];
    float* out = (float*)d_out;

    const int E = in_sizes[1];   // 800000 edges

    // 1) Repack weights
    repack_kernel<<<(N_OUT * N_FEAT + 255) / 256, 256>>>(W1w);

    // 2) Node projection GEMM on tensor cores (3xTF32)
    dim3 ggrid(N_OUT / BN, (N_NODES + BM - 1) / BM);
    gemm_tc_kernel<<<ggrid, 256>>>(h);

    // 3) Per-edge gather + relu-dot
    int warpsPerBlock = 256 / 32;
    int eblocks = (E + warpsPerBlock - 1) / warpsPerBlock;
    edge_kernel<<<eblocks, 256>>>(src, dst, W1b, W2w, W2b, out, E);
}

// round 4
// speedup vs baseline: 1.7907x; 1.7907x over previous
#include <cuda_runtime.h>
#include <cuda_bf16.h>
#include <cstdint>

// ---------------------------------------------------------------------------
// MLPLinkPredictor: score[e] = W2 . relu(W1 [h[src];h[dst]] + b1) + b2
//
// Identity: W1 [h_s; h_d] = W1a h_s + W1b h_d  (split W1 columns).
// => Precompute node projections C[n, 0:512] = h[n] @ Wt^T  (Wt repacked 512x256)
//    via tensor cores (bf16 hi/lo split: 3 MMAs recover ~fp32 accuracy),
//    then per edge a cheap gather + relu-dot.
// ---------------------------------------------------------------------------

#define N_NODES 50000
#define N_FEAT  256
#define N_OUT   512
#define N_NODES_PAD 50048      // multiple of 128

// Scratch (device globals: allocation-free per harness rules)
__device__ float         g_C [(size_t)N_NODES_PAD * N_OUT];   // ~102.5 MB
__device__ __nv_bfloat16 g_Ah[(size_t)N_NODES_PAD * N_FEAT];  // 25.6 MB
__device__ __nv_bfloat16 g_Al[(size_t)N_NODES_PAD * N_FEAT];  // 25.6 MB
__device__ __nv_bfloat16 g_Bh[(size_t)N_OUT * N_FEAT];        // 256 KB
__device__ __nv_bfloat16 g_Bl[(size_t)N_OUT * N_FEAT];        // 256 KB

// ---------------------------------------------------------------------------
// Split h into bf16 hi/lo. Rows >= N_NODES are zero-filled (padding).
// One float4 per thread.
// ---------------------------------------------------------------------------
__global__ void split_h_kernel(const float* __restrict__ h) {
    size_t i4 = (size_t)blockIdx.x * blockDim.x + threadIdx.x;
    size_t total4 = (size_t)N_NODES_PAD * N_FEAT / 4;
    if (i4 >= total4) return;
    size_t base = i4 * 4;
    size_t row = base / N_FEAT;

    float4 v = make_float4(0.f, 0.f, 0.f, 0.f);
    if (row < N_NODES) v = *reinterpret_cast<const float4*>(&h[base]);

    __nv_bfloat16 hi[4], lo[4];
    float x[4] = {v.x, v.y, v.z, v.w};
#pragma unroll
    for (int i = 0; i < 4; i++) {
        hi[i] = __float2bfloat16(x[i]);
        lo[i] = __float2bfloat16(x[i] - __bfloat162float(hi[i]));
    }
    *reinterpret_cast<uint2*>(&g_Ah[base]) = *reinterpret_cast<uint2*>(hi);
    *reinterpret_cast<uint2*>(&g_Al[base]) = *reinterpret_cast<uint2*>(lo);
}

// ---------------------------------------------------------------------------
// Repack W1_w [256, 512] into Wt [512, 256] and split into bf16 hi/lo.
//   Wt[j, k] = (j < 256) ? W1[j, k] : W1[j-256, 256 + k]   (k contiguous both ways)
// ---------------------------------------------------------------------------
__global__ void split_w_kernel(const float* __restrict__ W1) {
    size_t i4 = (size_t)blockIdx.x * blockDim.x + threadIdx.x;
    size_t total4 = (size_t)N_OUT * N_FEAT / 4;
    if (i4 >= total4) return;
    size_t base = i4 * 4;
    int j = (int)(base / N_FEAT);
    int k = (int)(base % N_FEAT);

    const float* srcp = (j < N_FEAT) ? &W1[(size_t)j * (2 * N_FEAT) + k]
                                     : &W1[(size_t)(j - N_FEAT) * (2 * N_FEAT) + N_FEAT + k];
    float4 v = *reinterpret_cast<const float4*>(srcp);

    __nv_bfloat16 hi[4], lo[4];
    float x[4] = {v.x, v.y, v.z, v.w};
#pragma unroll
    for (int i = 0; i < 4; i++) {
        hi[i] = __float2bfloat16(x[i]);
        lo[i] = __float2bfloat16(x[i] - __bfloat162float(hi[i]));
    }
    *reinterpret_cast<uint2*>(&g_Bh[base]) = *reinterpret_cast<uint2*>(hi);
    *reinterpret_cast<uint2*>(&g_Bl[base]) = *reinterpret_cast<uint2*>(lo);
}

// ---------------------------------------------------------------------------
// GEMM: g_C[50048, 512] = (Ah+Al)[50048,256] @ (Bh+Bl)[512,256]^T
// via mma.sync.m16n8k16 bf16, 3 terms: ah*bh + ah*bl + al*bh.
// Block 128x128, BK=32, 8 warps (2 along M x 4 along N), warp tile 64x32.
// ---------------------------------------------------------------------------
#define SK 40   // smem row stride in halves (32 + 8 pad) -> 80B rows, conflict-free

#define MMA_BF16(c, a, b)                                                          \
    asm volatile("mma.sync.aligned.m16n8k16.row.col.f32.bf16.bf16.f32 "            \
                 "{%0,%1,%2,%3}, {%4,%5,%6,%7}, {%8,%9}, {%0,%1,%2,%3};"           \
                 : "+f"((c)[0]), "+f"((c)[1]), "+f"((c)[2]), "+f"((c)[3])          \
                 : "r"((a)[0]), "r"((a)[1]), "r"((a)[2]), "r"((a)[3]),             \
                   "r"((b)[0]), "r"((b)[1]))

__global__ __launch_bounds__(256, 2)
void gemm_bf16split_kernel() {
    __shared__ __nv_bfloat16 sAh[128][SK];
    __shared__ __nv_bfloat16 sAl[128][SK];
    __shared__ __nv_bfloat16 sBh[128][SK];
    __shared__ __nv_bfloat16 sBl[128][SK];

    const int tid  = threadIdx.x;
    const int wid  = tid >> 5;
    const int lane = tid & 31;
    const int bn   = blockIdx.x;          // 0..3
    const int bm   = blockIdx.y;          // 0..390
    const int wm   = (wid & 1) * 64;      // warp M offset
    const int wn   = (wid >> 1) * 32;     // warp N offset
    const int g    = lane >> 2;           // groupID 0..7
    const int t    = lane & 3;            // threadID in group

    float acc[4][4][4];
#pragma unroll
    for (int mt = 0; mt < 4; mt++)
#pragma unroll
        for (int nt = 0; nt < 4; nt++)
#pragma unroll
            for (int i = 0; i < 4; i++) acc[mt][nt][i] = 0.f;

    // staging: each thread owns one uint4 (8 halves) per 64-row group
    const int lrow = tid >> 2;            // 0..63
    const int lcol = (tid & 3) * 8;       // 0,8,16,24 (halves)

    for (int k0 = 0; k0 < N_FEAT; k0 += 32) {
#pragma unroll
        for (int rr = 0; rr < 128; rr += 64) {
            int row = lrow + rr;
            size_t gA = (size_t)(bm * 128 + row) * N_FEAT + k0 + lcol;  // padded rows valid
            *reinterpret_cast<uint4*>(&sAh[row][lcol]) = *reinterpret_cast<const uint4*>(&g_Ah[gA]);
            *reinterpret_cast<uint4*>(&sAl[row][lcol]) = *reinterpret_cast<const uint4*>(&g_Al[gA]);
            size_t gB = (size_t)(bn * 128 + row) * N_FEAT + k0 + lcol;  // < 512 rows always
            *reinterpret_cast<uint4*>(&sBh[row][lcol]) = *reinterpret_cast<const uint4*>(&g_Bh[gB]);
            *reinterpret_cast<uint4*>(&sBl[row][lcol]) = *reinterpret_cast<const uint4*>(&g_Bl[gB]);
        }
        __syncthreads();

#pragma unroll
        for (int kk = 0; kk < 32; kk += 16) {
            const int c = kk + t * 2;
            uint32_t ah[4][4], al[4][4], bh[4][2], bl[4][2];
#pragma unroll
            for (int mt = 0; mt < 4; mt++) {
                int r0 = wm + mt * 16 + g;
                ah[mt][0] = *reinterpret_cast<uint32_t*>(&sAh[r0    ][c    ]);
                ah[mt][1] = *reinterpret_cast<uint32_t*>(&sAh[r0 + 8][c    ]);
                ah[mt][2] = *reinterpret_cast<uint32_t*>(&sAh[r0    ][c + 8]);
                ah[mt][3] = *reinterpret_cast<uint32_t*>(&sAh[r0 + 8][c + 8]);
                al[mt][0] = *reinterpret_cast<uint32_t*>(&sAl[r0    ][c    ]);
                al[mt][1] = *reinterpret_cast<uint32_t*>(&sAl[r0 + 8][c    ]);
                al[mt][2] = *reinterpret_cast<uint32_t*>(&sAl[r0    ][c + 8]);
                al[mt][3] = *reinterpret_cast<uint32_t*>(&sAl[r0 + 8][c + 8]);
            }
#pragma unroll
            for (int nt = 0; nt < 4; nt++) {
                int rn = wn + nt * 8 + g;
                bh[nt][0] = *reinterpret_cast<uint32_t*>(&sBh[rn][c    ]);
                bh[nt][1] = *reinterpret_cast<uint32_t*>(&sBh[rn][c + 8]);
                bl[nt][0] = *reinterpret_cast<uint32_t*>(&sBl[rn][c    ]);
                bl[nt][1] = *reinterpret_cast<uint32_t*>(&sBl[rn][c + 8]);
            }
#pragma unroll
            for (int mt = 0; mt < 4; mt++)
#pragma unroll
                for (int nt = 0; nt < 4; nt++) {
                    MMA_BF16(acc[mt][nt], ah[mt], bh[nt]);
                    MMA_BF16(acc[mt][nt], ah[mt], bl[nt]);
                    MMA_BF16(acc[mt][nt], al[mt], bh[nt]);
                }
        }
        __syncthreads();
    }

    // epilogue: padded rows make full stores safe
#pragma unroll
    for (int mt = 0; mt < 4; mt++) {
#pragma unroll
        for (int nt = 0; nt < 4; nt++) {
            int row0 = bm * 128 + wm + mt * 16 + g;
            int col  = bn * 128 + wn + nt * 8 + t * 2;
            float2 v01 = make_float2(acc[mt][nt][0], acc[mt][nt][1]);
            float2 v23 = make_float2(acc[mt][nt][2], acc[mt][nt][3]);
            *reinterpret_cast<float2*>(&g_C[(size_t)row0 * N_OUT + col])       = v01;
            *reinterpret_cast<float2*>(&g_C[(size_t)(row0 + 8) * N_OUT + col]) = v23;
        }
    }
}

// ---------------------------------------------------------------------------
// Edge kernel: one warp per edge.
//   hid[j] = relu(C[src, j] + C[dst, 256 + j] + b1[j]),  j in [0,256)
//   out[e] = dot(hid, W2) + b2
// ---------------------------------------------------------------------------
__global__ __launch_bounds__(256)
void edge_kernel(const int* __restrict__ src, const int* __restrict__ dst,
                 const float* __restrict__ b1, const float* __restrict__ W2w,
                 const float* __restrict__ W2b, float* __restrict__ out, int E) {
    int warp = (blockIdx.x * blockDim.x + threadIdx.x) >> 5;
    int lane = threadIdx.x & 31;
    if (warp >= E) return;

    int s = src[warp];
    int d = dst[warp];

    const float4* Cs = reinterpret_cast<const float4*>(g_C + (size_t)s * N_OUT);
    const float4* Cd = reinterpret_cast<const float4*>(g_C + (size_t)d * N_OUT + N_FEAT);
    const float4* B1 = reinterpret_cast<const float4*>(b1);
    const float4* W2 = reinterpret_cast<const float4*>(W2w);

    float acc = 0.f;
#pragma unroll
    for (int p = 0; p < 2; p++) {
        int i = p * 32 + lane;
        float4 a  = Cs[i];
        float4 b  = Cd[i];
        float4 bb = B1[i];
        float4 w  = W2[i];
        float h0 = fmaxf(a.x + b.x + bb.x, 0.f);
        float h1 = fmaxf(a.y + b.y + bb.y, 0.f);
        float h2 = fmaxf(a.z + b.z + bb.z, 0.f);
        float h3 = fmaxf(a.w + b.w + bb.w, 0.f);
        acc = fmaf(h0, w.x, acc);
        acc = fmaf(h1, w.y, acc);
        acc = fmaf(h2, w.z, acc);
        acc = fmaf(h3, w.w, acc);
    }

#pragma unroll
    for (int off = 16; off; off >>= 1)
        acc += __shfl_down_sync(0xffffffffu, acc, off);

    if (lane == 0) out[warp] = acc + W2b[0];
}

// ---------------------------------------------------------------------------
extern "C" void kernel_launch(void* const* d_in, const int* in_sizes, int n_in,
                              void* d_out, int out_size) {
    const float* h    = (const float*)d_in[0];
    const int*   src  = (const int*)  d_in[1];
    const int*   dst  = (const int*)  d_in[2];
    const float* W1w  = (const float*)d_in[3];
    const float* W1b  = (const float*)d_in[4];
    const float* W2w  = (const float*)d_in[5];
    const float* W2b  = (const float*)d_in[6];
    float* out = (float*)d_out;

    const int E = in_sizes[1];   // 800000 edges

    // 1) Split/repack weights and features into bf16 hi/lo
    {
        size_t n4 = (size_t)N_NODES_PAD * N_FEAT / 4;
        split_h_kernel<<<(unsigned)((n4 + 255) / 256), 256>>>(h);
        size_t w4 = (size_t)N_OUT * N_FEAT / 4;
        split_w_kernel<<<(unsigned)((w4 + 255) / 256), 256>>>(W1w);
    }

    // 2) Node projection GEMM on tensor cores (bf16 hi/lo, 3 MMAs)
    dim3 ggrid(N_OUT / 128, N_NODES_PAD / 128);
    gemm_bf16split_kernel<<<ggrid, 256>>>();

    // 3) Per-edge gather + relu-dot
    int warpsPerBlock = 256 / 32;
    int eblocks = (E + warpsPerBlock - 1) / warpsPerBlock;
    edge_kernel<<<eblocks, 256>>>(src, dst, W1b, W2w, W2b, out, E);
}

// round 5
// speedup vs baseline: 2.9059x; 1.6228x over previous
#include <cuda_runtime.h>
#include <cuda_bf16.h>
#include <cuda_fp16.h>
#include <cstdint>

// ---------------------------------------------------------------------------
// MLPLinkPredictor: score[e] = W2 . relu(W1 [h[src];h[dst]] + b1) + b2
//
// W1 [h_s; h_d] = W1a h_s + W1b h_d. Precompute C[n,0:512] = h @ Wt^T (+b1 on
// first half) on tensor cores (bf16 hi/lo split, 3 MMAs ~ fp32 accuracy),
// store C in fp16 (51 MB -> L2-resident). Edge phase: gather + relu-dot with
// W2 held in registers.
// ---------------------------------------------------------------------------

#define N_NODES 50000
#define N_FEAT  256
#define N_OUT   512
#define N_NODES_PAD 50048
#define FULL 0xffffffffu

// Scratch (device globals: allocation-free per harness rules)
__device__ __half        g_Ch[(size_t)N_NODES_PAD * N_OUT];   // 51.2 MB
__device__ __nv_bfloat16 g_Ah[(size_t)N_NODES_PAD * N_FEAT];  // 25.6 MB
__device__ __nv_bfloat16 g_Al[(size_t)N_NODES_PAD * N_FEAT];  // 25.6 MB
__device__ __nv_bfloat16 g_Bh[(size_t)N_OUT * N_FEAT];        // 256 KB
__device__ __nv_bfloat16 g_Bl[(size_t)N_OUT * N_FEAT];        // 256 KB

// ---------------------------------------------------------------------------
__global__ void split_h_kernel(const float* __restrict__ h) {
    size_t i4 = (size_t)blockIdx.x * blockDim.x + threadIdx.x;
    size_t total4 = (size_t)N_NODES_PAD * N_FEAT / 4;
    if (i4 >= total4) return;
    size_t base = i4 * 4;
    size_t row = base / N_FEAT;

    float4 v = make_float4(0.f, 0.f, 0.f, 0.f);
    if (row < N_NODES) v = *reinterpret_cast<const float4*>(&h[base]);

    __nv_bfloat16 hi[4], lo[4];
    float x[4] = {v.x, v.y, v.z, v.w};
#pragma unroll
    for (int i = 0; i < 4; i++) {
        hi[i] = __float2bfloat16(x[i]);
        lo[i] = __float2bfloat16(x[i] - __bfloat162float(hi[i]));
    }
    *reinterpret_cast<uint2*>(&g_Ah[base]) = *reinterpret_cast<uint2*>(hi);
    *reinterpret_cast<uint2*>(&g_Al[base]) = *reinterpret_cast<uint2*>(lo);
}

__global__ void split_w_kernel(const float* __restrict__ W1) {
    size_t i4 = (size_t)blockIdx.x * blockDim.x + threadIdx.x;
    size_t total4 = (size_t)N_OUT * N_FEAT / 4;
    if (i4 >= total4) return;
    size_t base = i4 * 4;
    int j = (int)(base / N_FEAT);
    int k = (int)(base % N_FEAT);

    const float* srcp = (j < N_FEAT) ? &W1[(size_t)j * (2 * N_FEAT) + k]
                                     : &W1[(size_t)(j - N_FEAT) * (2 * N_FEAT) + N_FEAT + k];
    float4 v = *reinterpret_cast<const float4*>(srcp);

    __nv_bfloat16 hi[4], lo[4];
    float x[4] = {v.x, v.y, v.z, v.w};
#pragma unroll
    for (int i = 0; i < 4; i++) {
        hi[i] = __float2bfloat16(x[i]);
        lo[i] = __float2bfloat16(x[i] - __bfloat162float(hi[i]));
    }
    *reinterpret_cast<uint2*>(&g_Bh[base]) = *reinterpret_cast<uint2*>(hi);
    *reinterpret_cast<uint2*>(&g_Bl[base]) = *reinterpret_cast<uint2*>(lo);
}

// ---------------------------------------------------------------------------
// GEMM: C[50048,512] = (Ah+Al) @ (Bh+Bl)^T via mma.m16n8k16 bf16 (3 terms),
// ldmatrix fragment loads, fp16 output with b1 folded into cols [0,256).
// Block 128x128, BK=32, 8 warps (2M x 4N), warp tile 64x32.
// ---------------------------------------------------------------------------
#define SK 40   // smem row stride in halves (32+8): 20-word rows -> LDSM conflict-free

#define MMA_BF16(c, a, b)                                                          \
    asm volatile("mma.sync.aligned.m16n8k16.row.col.f32.bf16.bf16.f32 "            \
                 "{%0,%1,%2,%3}, {%4,%5,%6,%7}, {%8,%9}, {%0,%1,%2,%3};"           \
                 : "+f"((c)[0]), "+f"((c)[1]), "+f"((c)[2]), "+f"((c)[3])          \
                 : "r"((a)[0]), "r"((a)[1]), "r"((a)[2]), "r"((a)[3]),             \
                   "r"((b)[0]), "r"((b)[1]))

#define LDSM_X4(r, p)                                                              \
    do {                                                                           \
        uint32_t _ad = (uint32_t)__cvta_generic_to_shared(p);                      \
        asm volatile("ldmatrix.sync.aligned.m8n8.x4.shared.b16 {%0,%1,%2,%3}, [%4];" \
                     : "=r"((r)[0]), "=r"((r)[1]), "=r"((r)[2]), "=r"((r)[3])      \
                     : "r"(_ad));                                                  \
    } while (0)

__global__ __launch_bounds__(256, 2)
void gemm_bf16split_kernel(const float* __restrict__ b1) {
    __shared__ __nv_bfloat16 sAh[128][SK];
    __shared__ __nv_bfloat16 sAl[128][SK];
    __shared__ __nv_bfloat16 sBh[128][SK];
    __shared__ __nv_bfloat16 sBl[128][SK];

    const int tid  = threadIdx.x;
    const int wid  = tid >> 5;
    const int lane = tid & 31;
    const int bn   = blockIdx.x;          // 0..3
    const int bm   = blockIdx.y;          // 0..390
    const int wm   = (wid & 1) * 64;
    const int wn   = (wid >> 1) * 32;
    const int g    = lane >> 2;
    const int t    = lane & 3;
    const int lm   = lane >> 3;           // ldmatrix matrix-group 0..3
    const int lr8  = lane & 7;

    float acc[4][4][4];
#pragma unroll
    for (int mt = 0; mt < 4; mt++)
#pragma unroll
        for (int nt = 0; nt < 4; nt++)
#pragma unroll
            for (int i = 0; i < 4; i++) acc[mt][nt][i] = 0.f;

    const int lrow = tid >> 2;
    const int lcol = (tid & 3) * 8;

    for (int k0 = 0; k0 < N_FEAT; k0 += 32) {
#pragma unroll
        for (int rr = 0; rr < 128; rr += 64) {
            int row = lrow + rr;
            size_t gA = (size_t)(bm * 128 + row) * N_FEAT + k0 + lcol;
            *reinterpret_cast<uint4*>(&sAh[row][lcol]) = *reinterpret_cast<const uint4*>(&g_Ah[gA]);
            *reinterpret_cast<uint4*>(&sAl[row][lcol]) = *reinterpret_cast<const uint4*>(&g_Al[gA]);
            size_t gB = (size_t)(bn * 128 + row) * N_FEAT + k0 + lcol;
            *reinterpret_cast<uint4*>(&sBh[row][lcol]) = *reinterpret_cast<const uint4*>(&g_Bh[gB]);
            *reinterpret_cast<uint4*>(&sBl[row][lcol]) = *reinterpret_cast<const uint4*>(&g_Bl[gB]);
        }
        __syncthreads();

#pragma unroll
        for (int kk = 0; kk < 32; kk += 16) {
            uint32_t ah[4][4], al[4][4], bh[4][2], bl[4][2];

            // A fragments: matrices {rows+0/8} x {cols+0/8} via lane groups
#pragma unroll
            for (int mt = 0; mt < 4; mt++) {
                int r = wm + mt * 16 + (lm & 1) * 8 + lr8;
                int c = kk + (lm >> 1) * 8;
                LDSM_X4(ah[mt], &sAh[r][c]);
                LDSM_X4(al[mt], &sAl[r][c]);
            }
            // B fragments: one x4 covers two 8-row n-tiles x two k-halves
            {
                int c = kk + (lm & 1) * 8;
                int r0 = wn + (lm >> 1) * 8 + lr8;
                uint32_t rb[4];
                LDSM_X4(rb, &sBh[r0][c]);
                bh[0][0] = rb[0]; bh[0][1] = rb[1]; bh[1][0] = rb[2]; bh[1][1] = rb[3];
                LDSM_X4(rb, &sBh[r0 + 16][c]);
                bh[2][0] = rb[0]; bh[2][1] = rb[1]; bh[3][0] = rb[2]; bh[3][1] = rb[3];
                LDSM_X4(rb, &sBl[r0][c]);
                bl[0][0] = rb[0]; bl[0][1] = rb[1]; bl[1][0] = rb[2]; bl[1][1] = rb[3];
                LDSM_X4(rb, &sBl[r0 + 16][c]);
                bl[2][0] = rb[0]; bl[2][1] = rb[1]; bl[3][0] = rb[2]; bl[3][1] = rb[3];
            }

#pragma unroll
            for (int mt = 0; mt < 4; mt++)
#pragma unroll
                for (int nt = 0; nt < 4; nt++) {
                    MMA_BF16(acc[mt][nt], ah[mt], bh[nt]);
                    MMA_BF16(acc[mt][nt], ah[mt], bl[nt]);
                    MMA_BF16(acc[mt][nt], al[mt], bh[nt]);
                }
        }
        __syncthreads();
    }

    // epilogue: add b1 to cols [0,256), convert to fp16, store
#pragma unroll
    for (int mt = 0; mt < 4; mt++) {
#pragma unroll
        for (int nt = 0; nt < 4; nt++) {
            int row0 = bm * 128 + wm + mt * 16 + g;
            int col  = bn * 128 + wn + nt * 8 + t * 2;
            float bias0 = 0.f, bias1 = 0.f;
            if (col < N_FEAT) { bias0 = b1[col]; bias1 = b1[col + 1]; }
            __half2 v01 = __floats2half2_rn(acc[mt][nt][0] + bias0, acc[mt][nt][1] + bias1);
            __half2 v23 = __floats2half2_rn(acc[mt][nt][2] + bias0, acc[mt][nt][3] + bias1);
            *reinterpret_cast<__half2*>(&g_Ch[(size_t)row0 * N_OUT + col])       = v01;
            *reinterpret_cast<__half2*>(&g_Ch[(size_t)(row0 + 8) * N_OUT + col]) = v23;
        }
    }
}

// ---------------------------------------------------------------------------
// Edge kernel: one warp per 32-edge batch. W2 lives in 8 regs/lane (loaded
// once), b1 already folded into C, b2 in a reg. Per edge: two 16B gathers
// (fp16 C), relu-dot, butterfly reduce; batched coalesced store.
// ---------------------------------------------------------------------------
__global__ __launch_bounds__(256)
void edge_kernel(const int* __restrict__ src, const int* __restrict__ dst,
                 const float* __restrict__ W2w, const float* __restrict__ W2b,
                 float* __restrict__ out, int E) {
    int gtid = blockIdx.x * blockDim.x + threadIdx.x;
    int lane = gtid & 31;
    int warp = gtid >> 5;

    // per-lane W2 slice: elements [lane*8, lane*8+8)
    float4 w0 = reinterpret_cast<const float4*>(W2w)[lane * 2];
    float4 w1 = reinterpret_cast<const float4*>(W2w)[lane * 2 + 1];
    float b2 = W2b[0];

    int base = warp * 32;
    if (base >= E) return;
    int n = min(32, E - base);

    int sl = 0, dl = 0;
    if (lane < n) { sl = src[base + lane]; dl = dst[base + lane]; }

    float res = 0.f;
    for (int i = 0; i < n; i++) {
        int s = __shfl_sync(FULL, sl, i);
        int d = __shfl_sync(FULL, dl, i);

        uint4 va = *reinterpret_cast<const uint4*>(&g_Ch[(size_t)s * N_OUT + lane * 8]);
        uint4 vb = *reinterpret_cast<const uint4*>(&g_Ch[(size_t)d * N_OUT + N_FEAT + lane * 8]);
        const __half2* ha = reinterpret_cast<const __half2*>(&va);
        const __half2* hb = reinterpret_cast<const __half2*>(&vb);

        float acc = 0.f;
        float2 fa, fb;
        fa = __half22float2(ha[0]); fb = __half22float2(hb[0]);
        acc = fmaf(fmaxf(fa.x + fb.x, 0.f), w0.x, acc);
        acc = fmaf(fmaxf(fa.y + fb.y, 0.f), w0.y, acc);
        fa = __half22float2(ha[1]); fb = __half22float2(hb[1]);
        acc = fmaf(fmaxf(fa.x + fb.x, 0.f), w0.z, acc);
        acc = fmaf(fmaxf(fa.y + fb.y, 0.f), w0.w, acc);
        fa = __half22float2(ha[2]); fb = __half22float2(hb[2]);
        acc = fmaf(fmaxf(fa.x + fb.x, 0.f), w1.x, acc);
        acc = fmaf(fmaxf(fa.y + fb.y, 0.f), w1.y, acc);
        fa = __half22float2(ha[3]); fb = __half22float2(hb[3]);
        acc = fmaf(fmaxf(fa.x + fb.x, 0.f), w1.z, acc);
        acc = fmaf(fmaxf(fa.y + fb.y, 0.f), w1.w, acc);

#pragma unroll
        for (int off = 16; off; off >>= 1)
            acc += __shfl_xor_sync(FULL, acc, off);

        if (lane == i) res = acc + b2;
    }
    if (lane < n) out[base + lane] = res;
}

// ---------------------------------------------------------------------------
extern "C" void kernel_launch(void* const* d_in, const int* in_sizes, int n_in,
                              void* d_out, int out_size) {
    const float* h    = (const float*)d_in[0];
    const int*   src  = (const int*)  d_in[1];
    const int*   dst  = (const int*)  d_in[2];
    const float* W1w  = (const float*)d_in[3];
    const float* W1b  = (const float*)d_in[4];
    const float* W2w  = (const float*)d_in[5];
    const float* W2b  = (const float*)d_in[6];
    float* out = (float*)d_out;

    const int E = in_sizes[1];   // 800000 edges

    // 1) Split/repack weights and features into bf16 hi/lo
    {
        size_t n4 = (size_t)N_NODES_PAD * N_FEAT / 4;
        split_h_kernel<<<(unsigned)((n4 + 255) / 256), 256>>>(h);
        size_t w4 = (size_t)N_OUT * N_FEAT / 4;
        split_w_kernel<<<(unsigned)((w4 + 255) / 256), 256>>>(W1w);
    }

    // 2) Node projection GEMM (bf16 hi/lo, ldmatrix, fp16 out, b1 folded)
    dim3 ggrid(N_OUT / 128, N_NODES_PAD / 128);
    gemm_bf16split_kernel<<<ggrid, 256>>>(W1b);

    // 3) Per-edge gather + relu-dot: one warp per 32 edges
    int nwarps  = (E + 31) / 32;
    int eblocks = (nwarps + 7) / 8;          // 8 warps per 256-thread block
    edge_kernel<<<eblocks, 256>>>(src, dst, W2w, W2b, out, E);
}

// round 6
// speedup vs baseline: 2.9789x; 1.0251x over previous
#include <cuda_runtime.h>
#include <cuda_bf16.h>
#include <cuda_fp16.h>
#include <cstdint>

// ---------------------------------------------------------------------------
// MLPLinkPredictor: score[e] = W2 . relu(W1 [h[src];h[dst]] + b1) + b2
//
// W1 [h_s; h_d] = W1a h_s + W1b h_d. Precompute C[n,0:512] = h @ Wt^T (+b1 on
// first half) on tensor cores (bf16 hi/lo split, 3 MMAs ~ fp32 accuracy),
// fp32->bf16 split fused into the GEMM stage (register prefetch pipeline).
// C stored fp16 (51 MB, L2-resident). Edge phase: half2 gather+relu-dot with
// W2 in registers and a 32-value butterfly transpose-reduce.
// ---------------------------------------------------------------------------

#define N_NODES 50000
#define N_FEAT  256
#define N_OUT   512
#define N_NODES_PAD 50048
#define FULL 0xffffffffu

// Scratch (device globals: allocation-free per harness rules)
__device__ __half        g_Ch[(size_t)N_NODES_PAD * N_OUT];   // 51.2 MB
__device__ __nv_bfloat16 g_Bh[(size_t)N_OUT * N_FEAT];        // 256 KB
__device__ __nv_bfloat16 g_Bl[(size_t)N_OUT * N_FEAT];        // 256 KB

// ---------------------------------------------------------------------------
// Repack W1_w [256,512] into Wt [512,256] and split into bf16 hi/lo.
// ---------------------------------------------------------------------------
__global__ void split_w_kernel(const float* __restrict__ W1) {
    size_t i4 = (size_t)blockIdx.x * blockDim.x + threadIdx.x;
    size_t total4 = (size_t)N_OUT * N_FEAT / 4;
    if (i4 >= total4) return;
    size_t base = i4 * 4;
    int j = (int)(base / N_FEAT);
    int k = (int)(base % N_FEAT);

    const float* srcp = (j < N_FEAT) ? &W1[(size_t)j * (2 * N_FEAT) + k]
                                     : &W1[(size_t)(j - N_FEAT) * (2 * N_FEAT) + N_FEAT + k];
    float4 v = *reinterpret_cast<const float4*>(srcp);

    __nv_bfloat16 hi[4], lo[4];
    float x[4] = {v.x, v.y, v.z, v.w};
#pragma unroll
    for (int i = 0; i < 4; i++) {
        hi[i] = __float2bfloat16(x[i]);
        lo[i] = __float2bfloat16(x[i] - __bfloat162float(hi[i]));
    }
    *reinterpret_cast<uint2*>(&g_Bh[base]) = *reinterpret_cast<uint2*>(hi);
    *reinterpret_cast<uint2*>(&g_Bl[base]) = *reinterpret_cast<uint2*>(lo);
}

// ---------------------------------------------------------------------------
// fp32x8 -> bf16 hi/lo x8 (packed conversions)
// ---------------------------------------------------------------------------
__device__ __forceinline__ void cvt8_hilo(const float4& f0, const float4& f1,
                                          uint4& hi, uint4& lo) {
    float fx[8] = {f0.x, f0.y, f0.z, f0.w, f1.x, f1.y, f1.z, f1.w};
    __nv_bfloat162 h[4], l[4];
#pragma unroll
    for (int i = 0; i < 4; i++) {
        h[i] = __floats2bfloat162_rn(fx[2 * i], fx[2 * i + 1]);
        float2 hf = __bfloat1622float2(h[i]);
        l[i] = __floats2bfloat162_rn(fx[2 * i] - hf.x, fx[2 * i + 1] - hf.y);
    }
    hi = *reinterpret_cast<uint4*>(h);
    lo = *reinterpret_cast<uint4*>(l);
}

// ---------------------------------------------------------------------------
// GEMM: C[50048,512] = (Ah+Al) @ (Bh+Bl)^T via mma.m16n8k16 bf16 (3 terms).
// A split computed in-register from fp32 h. Register-prefetch pipeline hides
// global latency. Block 128x128, BK=32, 8 warps (2M x 4N), warp tile 64x32.
// fp16 output with b1 folded into cols [0,256).
// ---------------------------------------------------------------------------
#define SK 40

#define MMA_BF16(c, a, b)                                                          \
    asm volatile("mma.sync.aligned.m16n8k16.row.col.f32.bf16.bf16.f32 "            \
                 "{%0,%1,%2,%3}, {%4,%5,%6,%7}, {%8,%9}, {%0,%1,%2,%3};"           \
                 : "+f"((c)[0]), "+f"((c)[1]), "+f"((c)[2]), "+f"((c)[3])          \
                 : "r"((a)[0]), "r"((a)[1]), "r"((a)[2]), "r"((a)[3]),             \
                   "r"((b)[0]), "r"((b)[1]))

#define LDSM_X4(r, p)                                                              \
    do {                                                                           \
        uint32_t _ad = (uint32_t)__cvta_generic_to_shared(p);                      \
        asm volatile("ldmatrix.sync.aligned.m8n8.x4.shared.b16 {%0,%1,%2,%3}, [%4];" \
                     : "=r"((r)[0]), "=r"((r)[1]), "=r"((r)[2]), "=r"((r)[3])      \
                     : "r"(_ad));                                                  \
    } while (0)

__global__ __launch_bounds__(256, 2)
void gemm_bf16split_kernel(const float* __restrict__ h, const float* __restrict__ b1) {
    __shared__ __nv_bfloat16 sAh[128][SK];
    __shared__ __nv_bfloat16 sAl[128][SK];
    __shared__ __nv_bfloat16 sBh[128][SK];
    __shared__ __nv_bfloat16 sBl[128][SK];

    const int tid  = threadIdx.x;
    const int wid  = tid >> 5;
    const int lane = tid & 31;
    const int bn   = blockIdx.x;          // 0..3
    const int bm   = blockIdx.y;          // 0..390
    const int wm   = (wid & 1) * 64;
    const int wn   = (wid >> 1) * 32;
    const int g    = lane >> 2;
    const int t    = lane & 3;
    const int lm   = lane >> 3;
    const int lr8  = lane & 7;

    float acc[4][4][4];
#pragma unroll
    for (int mt = 0; mt < 4; mt++)
#pragma unroll
        for (int nt = 0; nt < 4; nt++)
#pragma unroll
            for (int i = 0; i < 4; i++) acc[mt][nt][i] = 0.f;

    const int lrow = tid >> 2;            // 0..63
    const int fcol = (tid & 3) * 8;       // 8 floats / 8 halves per thread

    // prefetch registers
    float4 fa[2][2];
    uint4  pbh[2], pbl[2];

    // ---- prefetch k0 = 0 ----
#pragma unroll
    for (int rr = 0; rr < 2; rr++) {
        int row  = lrow + rr * 64;
        int grow = bm * 128 + row;
        if (grow < N_NODES) {
            const float* p = &h[(size_t)grow * N_FEAT + fcol];
            fa[rr][0] = *reinterpret_cast<const float4*>(p);
            fa[rr][1] = *reinterpret_cast<const float4*>(p + 4);
        } else {
            fa[rr][0] = make_float4(0.f, 0.f, 0.f, 0.f);
            fa[rr][1] = make_float4(0.f, 0.f, 0.f, 0.f);
        }
        size_t gB = (size_t)(bn * 128 + row) * N_FEAT + fcol;
        pbh[rr] = *reinterpret_cast<const uint4*>(&g_Bh[gB]);
        pbl[rr] = *reinterpret_cast<const uint4*>(&g_Bl[gB]);
    }

    for (int k0 = 0; k0 < N_FEAT; k0 += 32) {
        // ---- stage prefetched data into smem (convert A to hi/lo) ----
#pragma unroll
        for (int rr = 0; rr < 2; rr++) {
            int row = lrow + rr * 64;
            uint4 hi, lo;
            cvt8_hilo(fa[rr][0], fa[rr][1], hi, lo);
            *reinterpret_cast<uint4*>(&sAh[row][fcol]) = hi;
            *reinterpret_cast<uint4*>(&sAl[row][fcol]) = lo;
            *reinterpret_cast<uint4*>(&sBh[row][fcol]) = pbh[rr];
            *reinterpret_cast<uint4*>(&sBl[row][fcol]) = pbl[rr];
        }
        __syncthreads();

        // ---- prefetch next k-slice (overlaps with compute below) ----
        if (k0 + 32 < N_FEAT) {
            int kn = k0 + 32;
#pragma unroll
            for (int rr = 0; rr < 2; rr++) {
                int row  = lrow + rr * 64;
                int grow = bm * 128 + row;
                if (grow < N_NODES) {
                    const float* p = &h[(size_t)grow * N_FEAT + kn + fcol];
                    fa[rr][0] = *reinterpret_cast<const float4*>(p);
                    fa[rr][1] = *reinterpret_cast<const float4*>(p + 4);
                } else {
                    fa[rr][0] = make_float4(0.f, 0.f, 0.f, 0.f);
                    fa[rr][1] = make_float4(0.f, 0.f, 0.f, 0.f);
                }
                size_t gB = (size_t)(bn * 128 + row) * N_FEAT + kn + fcol;
                pbh[rr] = *reinterpret_cast<const uint4*>(&g_Bh[gB]);
                pbl[rr] = *reinterpret_cast<const uint4*>(&g_Bl[gB]);
            }
        }

        // ---- compute ----
#pragma unroll
        for (int kk = 0; kk < 32; kk += 16) {
            uint32_t ah[4][4], al[4][4], bh[4][2], bl[4][2];
#pragma unroll
            for (int mt = 0; mt < 4; mt++) {
                int r = wm + mt * 16 + (lm & 1) * 8 + lr8;
                int c = kk + (lm >> 1) * 8;
                LDSM_X4(ah[mt], &sAh[r][c]);
                LDSM_X4(al[mt], &sAl[r][c]);
            }
            {
                int c  = kk + (lm & 1) * 8;
                int r0 = wn + (lm >> 1) * 8 + lr8;
                uint32_t rb[4];
                LDSM_X4(rb, &sBh[r0][c]);
                bh[0][0] = rb[0]; bh[0][1] = rb[1]; bh[1][0] = rb[2]; bh[1][1] = rb[3];
                LDSM_X4(rb, &sBh[r0 + 16][c]);
                bh[2][0] = rb[0]; bh[2][1] = rb[1]; bh[3][0] = rb[2]; bh[3][1] = rb[3];
                LDSM_X4(rb, &sBl[r0][c]);
                bl[0][0] = rb[0]; bl[0][1] = rb[1]; bl[1][0] = rb[2]; bl[1][1] = rb[3];
                LDSM_X4(rb, &sBl[r0 + 16][c]);
                bl[2][0] = rb[0]; bl[2][1] = rb[1]; bl[3][0] = rb[2]; bl[3][1] = rb[3];
            }
#pragma unroll
            for (int mt = 0; mt < 4; mt++)
#pragma unroll
                for (int nt = 0; nt < 4; nt++) {
                    MMA_BF16(acc[mt][nt], ah[mt], bh[nt]);
                    MMA_BF16(acc[mt][nt], ah[mt], bl[nt]);
                    MMA_BF16(acc[mt][nt], al[mt], bh[nt]);
                }
        }
        __syncthreads();
    }

    // epilogue: add b1 to cols [0,256), convert to fp16, store
#pragma unroll
    for (int mt = 0; mt < 4; mt++) {
#pragma unroll
        for (int nt = 0; nt < 4; nt++) {
            int row0 = bm * 128 + wm + mt * 16 + g;
            int col  = bn * 128 + wn + nt * 8 + t * 2;
            float bias0 = 0.f, bias1 = 0.f;
            if (col < N_FEAT) { bias0 = b1[col]; bias1 = b1[col + 1]; }
            __half2 v01 = __floats2half2_rn(acc[mt][nt][0] + bias0, acc[mt][nt][1] + bias1);
            __half2 v23 = __floats2half2_rn(acc[mt][nt][2] + bias0, acc[mt][nt][3] + bias1);
            *reinterpret_cast<__half2*>(&g_Ch[(size_t)row0 * N_OUT + col])       = v01;
            *reinterpret_cast<__half2*>(&g_Ch[(size_t)(row0 + 8) * N_OUT + col]) = v23;
        }
    }
}

// ---------------------------------------------------------------------------
// Edge kernel: one warp per 32-edge batch. W2 in 8 regs/lane, b1 folded in C,
// half2 add+relu, fp32 dot, then a 32-value butterfly transpose-reduce
// (31 shfl per warp instead of 160). Lane l ends with edge l's score.
// ---------------------------------------------------------------------------
__global__ __launch_bounds__(256)
void edge_kernel(const int* __restrict__ src, const int* __restrict__ dst,
                 const float* __restrict__ W2w, const float* __restrict__ W2b,
                 float* __restrict__ out, int E) {
    int gtid = blockIdx.x * blockDim.x + threadIdx.x;
    int lane = gtid & 31;
    int warp = gtid >> 5;
    int base = warp * 32;
    if (base >= E) return;

    float4 w0 = reinterpret_cast<const float4*>(W2w)[lane * 2];
    float4 w1 = reinterpret_cast<const float4*>(W2w)[lane * 2 + 1];
    float wf[8] = {w0.x, w0.y, w0.z, w0.w, w1.x, w1.y, w1.z, w1.w};
    float b2 = W2b[0];

    int idx = base + lane;
    int sl = (idx < E) ? src[idx] : 0;
    int dl = (idx < E) ? dst[idx] : 0;

    const __half2 zero2 = __float2half2_rn(0.f);
    float v[32];

#pragma unroll
    for (int e = 0; e < 32; e++) {
        int s = __shfl_sync(FULL, sl, e);
        int d = __shfl_sync(FULL, dl, e);

        uint4 va = *reinterpret_cast<const uint4*>(&g_Ch[(size_t)s * N_OUT + lane * 8]);
        uint4 vb = *reinterpret_cast<const uint4*>(&g_Ch[(size_t)d * N_OUT + N_FEAT + lane * 8]);
        const __half2* ha = reinterpret_cast<const __half2*>(&va);
        const __half2* hb = reinterpret_cast<const __half2*>(&vb);

        float acc = 0.f;
#pragma unroll
        for (int j = 0; j < 4; j++) {
            __half2 tmax = __hmax2(__hadd2(ha[j], hb[j]), zero2);
            float2 f = __half22float2(tmax);
            acc = fmaf(f.x, wf[2 * j],     acc);
            acc = fmaf(f.y, wf[2 * j + 1], acc);
        }
        v[e] = acc;
    }

    // 32-value butterfly transpose-reduce: after 5 stages, lane l holds the
    // full 32-lane sum for edge l in v[0].
#pragma unroll
    for (int m = 16; m >= 1; m >>= 1) {
#pragma unroll
        for (int e = 0; e < m; e++) {
            float up   = (lane & m) ? v[e]     : v[e + m];
            float keep = (lane & m) ? v[e + m] : v[e];
            v[e] = keep + __shfl_xor_sync(FULL, up, m);
        }
    }

    if (base + lane < E) out[base + lane] = v[0] + b2;
}

// ---------------------------------------------------------------------------
extern "C" void kernel_launch(void* const* d_in, const int* in_sizes, int n_in,
                              void* d_out, int out_size) {
    const float* h    = (const float*)d_in[0];
    const int*   src  = (const int*)  d_in[1];
    const int*   dst  = (const int*)  d_in[2];
    const float* W1w  = (const float*)d_in[3];
    const float* W1b  = (const float*)d_in[4];
    const float* W2w  = (const float*)d_in[5];
    const float* W2b  = (const float*)d_in[6];
    float* out = (float*)d_out;

    const int E = in_sizes[1];   // 800000 edges

    // 1) Repack + split W1 into bf16 hi/lo (tiny)
    size_t w4 = (size_t)N_OUT * N_FEAT / 4;
    split_w_kernel<<<(unsigned)((w4 + 255) / 256), 256>>>(W1w);

    // 2) Node projection GEMM (fused fp32->bf16 split, reg-prefetch pipeline)
    dim3 ggrid(N_OUT / 128, N_NODES_PAD / 128);
    gemm_bf16split_kernel<<<ggrid, 256>>>(h, W1b);

    // 3) Per-edge gather + relu-dot: one warp per 32 edges
    int nwarps  = (E + 31) / 32;
    int eblocks = (nwarps + 7) / 8;
    edge_kernel<<<eblocks, 256>>>(src, dst, W2w, W2b, out, E);
}

// round 8
// speedup vs baseline: 3.8937x; 1.3071x over previous
#include <cuda_runtime.h>
#include <cuda_fp16.h>
#include <cstdint>

// ---------------------------------------------------------------------------
// MLPLinkPredictor: score[e] = W2 . relu(W1 [h[src];h[dst]] + b1) + b2
//
// W1 [h_s; h_d] = W1a h_s + W1b h_d. Precompute C[n,0:512] = h @ Wt^T (+b1 on
// first half) on tensor cores. Numerics: A = fp16(h) (single), B = fp16 hi/lo
// split (2 MMA terms), fp32 accumulate, fp16 C (51 MB, L2-resident).
// cp.async double-buffered mainloop. Edge phase: half2 gather + relu-dot,
// W2 in registers, butterfly transpose-reduce.
// ---------------------------------------------------------------------------

#define N_NODES 50000
#define N_FEAT  256
#define N_OUT   512
#define N_NODES_PAD 50048
#define FULL 0xffffffffu

// Scratch (device globals: allocation-free per harness rules)
__device__ __half g_Ch[(size_t)N_NODES_PAD * N_OUT];   // 51.2 MB
__device__ __half g_Af[(size_t)N_NODES_PAD * N_FEAT];  // 25.6 MB fp16 h (padded rows zero)
__device__ __half g_Bh[(size_t)N_OUT * N_FEAT];        // 256 KB
__device__ __half g_Bl[(size_t)N_OUT * N_FEAT];        // 256 KB

// ---------------------------------------------------------------------------
// h (fp32) -> g_Af (fp16), zero padding rows. 8 elements per thread.
// ---------------------------------------------------------------------------
__global__ void split_h_kernel(const float* __restrict__ h) {
    size_t i8 = ((size_t)blockIdx.x * blockDim.x + threadIdx.x) * 8;
    if (i8 >= (size_t)N_NODES_PAD * N_FEAT) return;
    size_t row = i8 / N_FEAT;

    __half hv[8];
    if (row < N_NODES) {
        float4 f0 = *reinterpret_cast<const float4*>(&h[i8]);
        float4 f1 = *reinterpret_cast<const float4*>(&h[i8 + 4]);
        float x[8] = {f0.x, f0.y, f0.z, f0.w, f1.x, f1.y, f1.z, f1.w};
#pragma unroll
        for (int i = 0; i < 8; i++) hv[i] = __float2half_rn(x[i]);
    } else {
#pragma unroll
        for (int i = 0; i < 8; i++) hv[i] = __ushort_as_half((unsigned short)0);
    }
    *reinterpret_cast<uint4*>(&g_Af[i8]) = *reinterpret_cast<uint4*>(hv);
}

// ---------------------------------------------------------------------------
// Repack W1_w [256,512] into Wt [512,256] and split into fp16 hi/lo.
//   Wt[j,k] = (j < 256) ? W1[j,k] : W1[j-256, 256+k]
// ---------------------------------------------------------------------------
__global__ void split_w_kernel(const float* __restrict__ W1) {
    size_t i4 = (size_t)blockIdx.x * blockDim.x + threadIdx.x;
    size_t total4 = (size_t)N_OUT * N_FEAT / 4;
    if (i4 >= total4) return;
    size_t base = i4 * 4;
    int j = (int)(base / N_FEAT);
    int k = (int)(base % N_FEAT);

    const float* srcp = (j < N_FEAT) ? &W1[(size_t)j * (2 * N_FEAT) + k]
                                     : &W1[(size_t)(j - N_FEAT) * (2 * N_FEAT) + N_FEAT + k];
    float4 v = *reinterpret_cast<const float4*>(srcp);

    __half hi[4], lo[4];
    float x[4] = {v.x, v.y, v.z, v.w};
#pragma unroll
    for (int i = 0; i < 4; i++) {
        hi[i] = __float2half_rn(x[i]);
        lo[i] = __float2half_rn(x[i] - __half2float(hi[i]));
    }
    *reinterpret_cast<uint2*>(&g_Bh[base]) = *reinterpret_cast<uint2*>(hi);
    *reinterpret_cast<uint2*>(&g_Bl[base]) = *reinterpret_cast<uint2*>(lo);
}

// ---------------------------------------------------------------------------
// GEMM: C[50048,512] = A @ (Bh+Bl)^T via mma.m16n8k16 fp16 (2 terms).
// cp.async 2-stage pipeline; block 128x128, BK=32, 8 warps (2M x 4N),
// warp tile 64x32. fp16 output with b1 folded into cols [0,256).
// ---------------------------------------------------------------------------
#define SK 40                      // 32 + 8 pad halves per smem row
#define TILE_H (128 * SK)          // halves per tile
#define BUF_H  (3 * TILE_H)        // A, Bh, Bl per stage

#define MMA_F16(c, a, b)                                                           \
    asm volatile("mma.sync.aligned.m16n8k16.row.col.f32.f16.f16.f32 "              \
                 "{%0,%1,%2,%3}, {%4,%5,%6,%7}, {%8,%9}, {%0,%1,%2,%3};"           \
                 : "+f"((c)[0]), "+f"((c)[1]), "+f"((c)[2]), "+f"((c)[3])          \
                 : "r"((a)[0]), "r"((a)[1]), "r"((a)[2]), "r"((a)[3]),             \
                   "r"((b)[0]), "r"((b)[1]))

#define LDSM_X4(r, p)                                                              \
    do {                                                                           \
        uint32_t _ad = (uint32_t)__cvta_generic_to_shared(p);                      \
        asm volatile("ldmatrix.sync.aligned.m8n8.x4.shared.b16 {%0,%1,%2,%3}, [%4];" \
                     : "=r"((r)[0]), "=r"((r)[1]), "=r"((r)[2]), "=r"((r)[3])      \
                     : "r"(_ad));                                                  \
    } while (0)

#define CP_ASYNC16(saddr, gptr)                                                    \
    asm volatile("{\n\t.reg .u64 g;\n\tcvta.to.global.u64 g, %1;\n\t"              \
                 "cp.async.cg.shared.global [%0], [g], 16;\n\t}"                   \
                 :: "r"(saddr), "l"(gptr))
#define CP_COMMIT() asm volatile("cp.async.commit_group;")
#define CP_WAIT1()  asm volatile("cp.async.wait_group 1;")
#define CP_WAIT0()  asm volatile("cp.async.wait_group 0;")

extern __shared__ __half sm_dyn[];

__device__ __forceinline__ void stage_chunk(uint32_t smem_base, int buf,
                                            int bm, int bn, int k0, int tid) {
    uint32_t b = smem_base + (uint32_t)buf * (BUF_H * 2);
#pragma unroll
    for (int rep = 0; rep < 2; rep++) {
        int chunk = tid + rep * 256;           // 0..511
        int row   = chunk >> 2;                // 0..127
        int c8    = (chunk & 3) * 8;           // halves
        uint32_t off = (uint32_t)(row * SK + c8) * 2;
        CP_ASYNC16(b + off,
                   &g_Af[(size_t)(bm * 128 + row) * N_FEAT + k0 + c8]);
        CP_ASYNC16(b + TILE_H * 2 + off,
                   &g_Bh[(size_t)(bn * 128 + row) * N_FEAT + k0 + c8]);
        CP_ASYNC16(b + 2 * TILE_H * 2 + off,
                   &g_Bl[(size_t)(bn * 128 + row) * N_FEAT + k0 + c8]);
    }
}

__global__ __launch_bounds__(256, 2)
void gemm_f16_kernel(const float* __restrict__ b1) {
    const int tid  = threadIdx.x;
    const int wid  = tid >> 5;
    const int lane = tid & 31;
    const int bn   = blockIdx.x;          // 0..3
    const int bm   = blockIdx.y;          // 0..390
    const int wm   = (wid & 1) * 64;
    const int wn   = (wid >> 1) * 32;
    const int g    = lane >> 2;
    const int t    = lane & 3;
    const int lm   = lane >> 3;
    const int lr8  = lane & 7;

    float acc[4][4][4];
#pragma unroll
    for (int mt = 0; mt < 4; mt++)
#pragma unroll
        for (int nt = 0; nt < 4; nt++)
#pragma unroll
            for (int i = 0; i < 4; i++) acc[mt][nt][i] = 0.f;

    uint32_t smb = (uint32_t)__cvta_generic_to_shared(sm_dyn);

    stage_chunk(smb, 0, bm, bn, 0, tid);  CP_COMMIT();
    stage_chunk(smb, 1, bm, bn, 32, tid); CP_COMMIT();

#pragma unroll 1
    for (int it = 0; it < 8; it++) {
        if (it < 7) CP_WAIT1(); else CP_WAIT0();
        __syncthreads();

        __half (*sA)[SK]  = reinterpret_cast<__half(*)[SK]>(sm_dyn + (it & 1) * BUF_H);
        __half (*sBh)[SK] = reinterpret_cast<__half(*)[SK]>(sm_dyn + (it & 1) * BUF_H + TILE_H);
        __half (*sBl)[SK] = reinterpret_cast<__half(*)[SK]>(sm_dyn + (it & 1) * BUF_H + 2 * TILE_H);

#pragma unroll
        for (int kk = 0; kk < 32; kk += 16) {
            uint32_t a[4][4], bh[4][2], bl[4][2];
#pragma unroll
            for (int mt = 0; mt < 4; mt++) {
                int r = wm + mt * 16 + (lm & 1) * 8 + lr8;
                int c = kk + (lm >> 1) * 8;
                LDSM_X4(a[mt], &sA[r][c]);
            }
            {
                int c  = kk + (lm & 1) * 8;
                int r0 = wn + (lm >> 1) * 8 + lr8;
                uint32_t rb[4];
                LDSM_X4(rb, &sBh[r0][c]);
                bh[0][0] = rb[0]; bh[0][1] = rb[1]; bh[1][0] = rb[2]; bh[1][1] = rb[3];
                LDSM_X4(rb, &sBh[r0 + 16][c]);
                bh[2][0] = rb[0]; bh[2][1] = rb[1]; bh[3][0] = rb[2]; bh[3][1] = rb[3];
                LDSM_X4(rb, &sBl[r0][c]);
                bl[0][0] = rb[0]; bl[0][1] = rb[1]; bl[1][0] = rb[2]; bl[1][1] = rb[3];
                LDSM_X4(rb, &sBl[r0 + 16][c]);
                bl[2][0] = rb[0]; bl[2][1] = rb[1]; bl[3][0] = rb[2]; bl[3][1] = rb[3];
            }
#pragma unroll
            for (int mt = 0; mt < 4; mt++)
#pragma unroll
                for (int nt = 0; nt < 4; nt++) {
                    MMA_F16(acc[mt][nt], a[mt], bh[nt]);
                    MMA_F16(acc[mt][nt], a[mt], bl[nt]);
                }
        }
        __syncthreads();

        if (it + 2 < 8) {
            stage_chunk(smb, it & 1, bm, bn, (it + 2) * 32, tid);
            CP_COMMIT();
        }
    }

    // epilogue: add b1 to cols [0,256), convert to fp16, store
#pragma unroll
    for (int mt = 0; mt < 4; mt++) {
#pragma unroll
        for (int nt = 0; nt < 4; nt++) {
            int row0 = bm * 128 + wm + mt * 16 + g;
            int col  = bn * 128 + wn + nt * 8 + t * 2;
            float bias0 = 0.f, bias1 = 0.f;
            if (col < N_FEAT) { bias0 = b1[col]; bias1 = b1[col + 1]; }
            __half2 v01 = __floats2half2_rn(acc[mt][nt][0] + bias0, acc[mt][nt][1] + bias1);
            __half2 v23 = __floats2half2_rn(acc[mt][nt][2] + bias0, acc[mt][nt][3] + bias1);
            *reinterpret_cast<__half2*>(&g_Ch[(size_t)row0 * N_OUT + col])       = v01;
            *reinterpret_cast<__half2*>(&g_Ch[(size_t)(row0 + 8) * N_OUT + col]) = v23;
        }
    }
}

// ---------------------------------------------------------------------------
// Edge kernel: one warp per 32-edge batch (L2-bandwidth bound; ~819 MB total).
// W2 in 8 regs/lane, b1 folded in C, half2 add+relu, fp32 dot, 32-value
// butterfly transpose-reduce. Lane l ends with edge l's score.
// ---------------------------------------------------------------------------
__global__ __launch_bounds__(256)
void edge_kernel(const int* __restrict__ src, const int* __restrict__ dst,
                 const float* __restrict__ W2w, const float* __restrict__ W2b,
                 float* __restrict__ out, int E) {
    int gtid = blockIdx.x * blockDim.x + threadIdx.x;
    int lane = gtid & 31;
    int warp = gtid >> 5;
    int base = warp * 32;
    if (base >= E) return;

    float4 w0 = reinterpret_cast<const float4*>(W2w)[lane * 2];
    float4 w1 = reinterpret_cast<const float4*>(W2w)[lane * 2 + 1];
    float wf[8] = {w0.x, w0.y, w0.z, w0.w, w1.x, w1.y, w1.z, w1.w};
    float b2 = W2b[0];

    int idx = base + lane;
    int sl = (idx < E) ? src[idx] : 0;
    int dl = (idx < E) ? dst[idx] : 0;

    const __half2 zero2 = __float2half2_rn(0.f);
    float v[32];

#pragma unroll
    for (int e = 0; e < 32; e++) {
        int s = __shfl_sync(FULL, sl, e);
        int d = __shfl_sync(FULL, dl, e);

        uint4 va = *reinterpret_cast<const uint4*>(&g_Ch[(size_t)s * N_OUT + lane * 8]);
        uint4 vb = *reinterpret_cast<const uint4*>(&g_Ch[(size_t)d * N_OUT + N_FEAT + lane * 8]);
        const __half2* ha = reinterpret_cast<const __half2*>(&va);
        const __half2* hb = reinterpret_cast<const __half2*>(&vb);

        float acc = 0.f;
#pragma unroll
        for (int j = 0; j < 4; j++) {
            __half2 tmax = __hmax2(__hadd2(ha[j], hb[j]), zero2);
            float2 f = __half22float2(tmax);
            acc = fmaf(f.x, wf[2 * j],     acc);
            acc = fmaf(f.y, wf[2 * j + 1], acc);
        }
        v[e] = acc;
    }

#pragma unroll
    for (int m = 16; m >= 1; m >>= 1) {
#pragma unroll
        for (int e = 0; e < m; e++) {
            float up   = (lane & m) ? v[e]     : v[e + m];
            float keep = (lane & m) ? v[e + m] : v[e];
            v[e] = keep + __shfl_xor_sync(FULL, up, m);
        }
    }

    if (base + lane < E) out[base + lane] = v[0] + b2;
}

// ---------------------------------------------------------------------------
extern "C" void kernel_launch(void* const* d_in, const int* in_sizes, int n_in,
                              void* d_out, int out_size) {
    const float* h    = (const float*)d_in[0];
    const int*   src  = (const int*)  d_in[1];
    const int*   dst  = (const int*)  d_in[2];
    const float* W1w  = (const float*)d_in[3];
    const float* W1b  = (const float*)d_in[4];
    const float* W2w  = (const float*)d_in[5];
    const float* W2b  = (const float*)d_in[6];
    float* out = (float*)d_out;

    const int E = in_sizes[1];   // 800000 edges

    // 1) fp16 conversions / weight repack+split
    size_t n8 = (size_t)N_NODES_PAD * N_FEAT / 8;
    split_h_kernel<<<(unsigned)((n8 + 255) / 256), 256>>>(h);
    size_t w4 = (size_t)N_OUT * N_FEAT / 4;
    split_w_kernel<<<(unsigned)((w4 + 255) / 256), 256>>>(W1w);

    // 2) Node projection GEMM (fp16 2-term, cp.async double buffered)
    static int smem_set = 0;
    const int smem_bytes = 2 * BUF_H * 2;   // 2 stages * (A,Bh,Bl) bytes = 61440
    if (!smem_set) {
        cudaFuncSetAttribute(gemm_f16_kernel,
                             cudaFuncAttributeMaxDynamicSharedMemorySize, smem_bytes);
        smem_set = 1;
    }
    dim3 ggrid(N_OUT / 128, N_NODES_PAD / 128);
    gemm_f16_kernel<<<ggrid, 256, smem_bytes>>>(W1b);

    // 3) Per-edge gather + relu-dot: one warp per 32 edges
    int nwarps  = (E + 31) / 32;
    int eblocks = (nwarps + 7) / 8;
    edge_kernel<<<eblocks, 256>>>(src, dst, W2w, W2b, out, E);
}

// round 9
// speedup vs baseline: 4.8543x; 1.2467x over previous
#include <cuda_runtime.h>
#include <cuda_fp16.h>
#include <cstdint>

// ---------------------------------------------------------------------------
// MLPLinkPredictor: score[e] = W2 . relu(W1 [h[src];h[dst]] + b1) + b2
//
// W1 [h_s; h_d] = W1a h_s + W1b h_d. Precompute C[n,0:512] = h @ Wt^T (+b1 on
// first half) on tensor cores. Numerics: A = fp16(h), B = fp16(Wt), fp32
// accumulate, fp16 C (51 MB, L2-resident). Error budget: three equal fp16
// quantization sources (~8e-5 rms on hid each) -> rel_err ~5e-4 < 1e-3.
// cp.async 3-stage pipeline. Edge phase: half2 gather + relu-dot, W2 in
// registers, 16-edge butterfly transpose-reduce.
// ---------------------------------------------------------------------------

#define N_NODES 50000
#define N_FEAT  256
#define N_OUT   512
#define N_NODES_PAD 50048
#define FULL 0xffffffffu

// Scratch (device globals: allocation-free per harness rules)
__device__ __half g_Ch[(size_t)N_NODES_PAD * N_OUT];   // 51.2 MB
__device__ __half g_Af[(size_t)N_NODES_PAD * N_FEAT];  // 25.6 MB fp16 h (padded rows zero)
__device__ __half g_Bf[(size_t)N_OUT * N_FEAT];        // 256 KB fp16 repacked W1

// ---------------------------------------------------------------------------
// h (fp32) -> g_Af (fp16), zero padding rows. 8 elements per thread.
// ---------------------------------------------------------------------------
__global__ void split_h_kernel(const float* __restrict__ h) {
    size_t i8 = ((size_t)blockIdx.x * blockDim.x + threadIdx.x) * 8;
    if (i8 >= (size_t)N_NODES_PAD * N_FEAT) return;
    size_t row = i8 / N_FEAT;

    __half hv[8];
    if (row < N_NODES) {
        float4 f0 = *reinterpret_cast<const float4*>(&h[i8]);
        float4 f1 = *reinterpret_cast<const float4*>(&h[i8 + 4]);
        float x[8] = {f0.x, f0.y, f0.z, f0.w, f1.x, f1.y, f1.z, f1.w};
#pragma unroll
        for (int i = 0; i < 8; i++) hv[i] = __float2half_rn(x[i]);
    } else {
#pragma unroll
        for (int i = 0; i < 8; i++) hv[i] = __ushort_as_half((unsigned short)0);
    }
    *reinterpret_cast<uint4*>(&g_Af[i8]) = *reinterpret_cast<uint4*>(hv);
}

// ---------------------------------------------------------------------------
// Repack W1_w [256,512] into Wt [512,256] fp16.
//   Wt[j,k] = (j < 256) ? W1[j,k] : W1[j-256, 256+k]
// ---------------------------------------------------------------------------
__global__ void split_w_kernel(const float* __restrict__ W1) {
    size_t i4 = (size_t)blockIdx.x * blockDim.x + threadIdx.x;
    size_t total4 = (size_t)N_OUT * N_FEAT / 4;
    if (i4 >= total4) return;
    size_t base = i4 * 4;
    int j = (int)(base / N_FEAT);
    int k = (int)(base % N_FEAT);

    const float* srcp = (j < N_FEAT) ? &W1[(size_t)j * (2 * N_FEAT) + k]
                                     : &W1[(size_t)(j - N_FEAT) * (2 * N_FEAT) + N_FEAT + k];
    float4 v = *reinterpret_cast<const float4*>(srcp);

    __half hv[4];
    float x[4] = {v.x, v.y, v.z, v.w};
#pragma unroll
    for (int i = 0; i < 4; i++) hv[i] = __float2half_rn(x[i]);
    *reinterpret_cast<uint2*>(&g_Bf[base]) = *reinterpret_cast<uint2*>(hv);
}

// ---------------------------------------------------------------------------
// GEMM: C[50048,512] = A @ B^T via mma.m16n8k16 fp16, fp32 accum.
// cp.async 3-stage pipeline (stage-before-compute); block 128x128, BK=32,
// 8 warps (2M x 4N), warp tile 64x32. fp16 out, b1 folded into cols [0,256).
// ---------------------------------------------------------------------------
#define SK 40                      // 32 + 8 pad halves per smem row
#define TILE_H (128 * SK)          // halves per tile
#define BUF_H  (2 * TILE_H)        // A, B per stage

#define MMA_F16(c, a, b)                                                           \
    asm volatile("mma.sync.aligned.m16n8k16.row.col.f32.f16.f16.f32 "              \
                 "{%0,%1,%2,%3}, {%4,%5,%6,%7}, {%8,%9}, {%0,%1,%2,%3};"           \
                 : "+f"((c)[0]), "+f"((c)[1]), "+f"((c)[2]), "+f"((c)[3])          \
                 : "r"((a)[0]), "r"((a)[1]), "r"((a)[2]), "r"((a)[3]),             \
                   "r"((b)[0]), "r"((b)[1]))

#define LDSM_X4(r, p)                                                              \
    do {                                                                           \
        uint32_t _ad = (uint32_t)__cvta_generic_to_shared(p);                      \
        asm volatile("ldmatrix.sync.aligned.m8n8.x4.shared.b16 {%0,%1,%2,%3}, [%4];" \
                     : "=r"((r)[0]), "=r"((r)[1]), "=r"((r)[2]), "=r"((r)[3])      \
                     : "r"(_ad));                                                  \
    } while (0)

#define CP_ASYNC16(saddr, gptr)                                                    \
    asm volatile("{\n\t.reg .u64 g;\n\tcvta.to.global.u64 g, %1;\n\t"              \
                 "cp.async.cg.shared.global [%0], [g], 16;\n\t}"                   \
                 :: "r"(saddr), "l"(gptr))
#define CP_COMMIT() asm volatile("cp.async.commit_group;")
#define CP_WAIT1()  asm volatile("cp.async.wait_group 1;")
#define CP_WAIT0()  asm volatile("cp.async.wait_group 0;")

extern __shared__ __half sm_dyn[];

__device__ __forceinline__ void stage_chunk(uint32_t smem_base, int buf,
                                            int bm, int bn, int k0, int tid) {
    uint32_t b = smem_base + (uint32_t)buf * (BUF_H * 2);
#pragma unroll
    for (int rep = 0; rep < 2; rep++) {
        int chunk = tid + rep * 256;           // 0..511
        int row   = chunk >> 2;                // 0..127
        int c8    = (chunk & 3) * 8;           // halves
        uint32_t off = (uint32_t)(row * SK + c8) * 2;
        CP_ASYNC16(b + off,
                   &g_Af[(size_t)(bm * 128 + row) * N_FEAT + k0 + c8]);
        CP_ASYNC16(b + TILE_H * 2 + off,
                   &g_Bf[(size_t)(bn * 128 + row) * N_FEAT + k0 + c8]);
    }
}

__global__ __launch_bounds__(256, 2)
void gemm_f16_kernel(const float* __restrict__ b1) {
    const int tid  = threadIdx.x;
    const int wid  = tid >> 5;
    const int lane = tid & 31;
    const int bn   = blockIdx.x;          // 0..3
    const int bm   = blockIdx.y;          // 0..390
    const int wm   = (wid & 1) * 64;
    const int wn   = (wid >> 1) * 32;
    const int g    = lane >> 2;
    const int t    = lane & 3;
    const int lm   = lane >> 3;
    const int lr8  = lane & 7;

    float acc[4][4][4];
#pragma unroll
    for (int mt = 0; mt < 4; mt++)
#pragma unroll
        for (int nt = 0; nt < 4; nt++)
#pragma unroll
            for (int i = 0; i < 4; i++) acc[mt][nt][i] = 0.f;

    uint32_t smb = (uint32_t)__cvta_generic_to_shared(sm_dyn);

    stage_chunk(smb, 0, bm, bn, 0, tid);  CP_COMMIT();
    stage_chunk(smb, 1, bm, bn, 32, tid); CP_COMMIT();

#pragma unroll 1
    for (int it = 0; it < 8; it++) {
        if (it < 7) CP_WAIT1(); else CP_WAIT0();
        __syncthreads();

        // stage chunk it+2 into buffer (it+2)%3 BEFORE computing chunk it:
        // two full compute phases hide its latency. Safe: buffer (it+2)%3
        // held chunk it-1, whose compute finished before the barrier above.
        if (it + 2 < 8) {
            stage_chunk(smb, (it + 2) % 3, bm, bn, (it + 2) * 32, tid);
            CP_COMMIT();
        }

        __half (*sA)[SK] = reinterpret_cast<__half(*)[SK]>(sm_dyn + (it % 3) * BUF_H);
        __half (*sB)[SK] = reinterpret_cast<__half(*)[SK]>(sm_dyn + (it % 3) * BUF_H + TILE_H);

#pragma unroll
        for (int kk = 0; kk < 32; kk += 16) {
            uint32_t a[4][4], bh[4][2];
#pragma unroll
            for (int mt = 0; mt < 4; mt++) {
                int r = wm + mt * 16 + (lm & 1) * 8 + lr8;
                int c = kk + (lm >> 1) * 8;
                LDSM_X4(a[mt], &sA[r][c]);
            }
            {
                int c  = kk + (lm & 1) * 8;
                int r0 = wn + (lm >> 1) * 8 + lr8;
                uint32_t rb[4];
                LDSM_X4(rb, &sB[r0][c]);
                bh[0][0] = rb[0]; bh[0][1] = rb[1]; bh[1][0] = rb[2]; bh[1][1] = rb[3];
                LDSM_X4(rb, &sB[r0 + 16][c]);
                bh[2][0] = rb[0]; bh[2][1] = rb[1]; bh[3][0] = rb[2]; bh[3][1] = rb[3];
            }
#pragma unroll
            for (int mt = 0; mt < 4; mt++)
#pragma unroll
                for (int nt = 0; nt < 4; nt++)
                    MMA_F16(acc[mt][nt], a[mt], bh[nt]);
        }
        __syncthreads();
    }

    // epilogue: add b1 to cols [0,256), convert to fp16, store
#pragma unroll
    for (int mt = 0; mt < 4; mt++) {
#pragma unroll
        for (int nt = 0; nt < 4; nt++) {
            int row0 = bm * 128 + wm + mt * 16 + g;
            int col  = bn * 128 + wn + nt * 8 + t * 2;
            float bias0 = 0.f, bias1 = 0.f;
            if (col < N_FEAT) { bias0 = b1[col]; bias1 = b1[col + 1]; }
            __half2 v01 = __floats2half2_rn(acc[mt][nt][0] + bias0, acc[mt][nt][1] + bias1);
            __half2 v23 = __floats2half2_rn(acc[mt][nt][2] + bias0, acc[mt][nt][3] + bias1);
            *reinterpret_cast<__half2*>(&g_Ch[(size_t)row0 * N_OUT + col])       = v01;
            *reinterpret_cast<__half2*>(&g_Ch[(size_t)(row0 + 8) * N_OUT + col]) = v23;
        }
    }
}

// ---------------------------------------------------------------------------
// Edge kernel: one warp per 16-edge batch (fewer regs -> higher occupancy ->
// more outstanding gathers at L2). W2 in 8 regs/lane, b1 folded in C, half2
// add+relu, fp32 dot, 16-value butterfly transpose-reduce: lanes l and l+16
// each reduce their 16-lane half for edge (l&15), final xor-16 fold.
// ---------------------------------------------------------------------------
__global__ __launch_bounds__(256)
void edge_kernel(const int* __restrict__ src, const int* __restrict__ dst,
                 const float* __restrict__ W2w, const float* __restrict__ W2b,
                 float* __restrict__ out, int E) {
    int gtid = blockIdx.x * blockDim.x + threadIdx.x;
    int lane = gtid & 31;
    int warp = gtid >> 5;
    int base = warp * 16;
    if (base >= E) return;

    float4 w0 = reinterpret_cast<const float4*>(W2w)[lane * 2];
    float4 w1 = reinterpret_cast<const float4*>(W2w)[lane * 2 + 1];
    float wf[8] = {w0.x, w0.y, w0.z, w0.w, w1.x, w1.y, w1.z, w1.w};
    float b2 = W2b[0];

    int idx = base + (lane & 15);
    int sl = (idx < E) ? src[idx] : 0;
    int dl = (idx < E) ? dst[idx] : 0;

    const __half2 zero2 = __float2half2_rn(0.f);
    float v[16];

#pragma unroll
    for (int e = 0; e < 16; e++) {
        int s = __shfl_sync(FULL, sl, e);
        int d = __shfl_sync(FULL, dl, e);

        uint4 va = *reinterpret_cast<const uint4*>(&g_Ch[(size_t)s * N_OUT + lane * 8]);
        uint4 vb = *reinterpret_cast<const uint4*>(&g_Ch[(size_t)d * N_OUT + N_FEAT + lane * 8]);
        const __half2* ha = reinterpret_cast<const __half2*>(&va);
        const __half2* hb = reinterpret_cast<const __half2*>(&vb);

        float acc = 0.f;
#pragma unroll
        for (int j = 0; j < 4; j++) {
            __half2 tmax = __hmax2(__hadd2(ha[j], hb[j]), zero2);
            float2 f = __half22float2(tmax);
            acc = fmaf(f.x, wf[2 * j],     acc);
            acc = fmaf(f.y, wf[2 * j + 1], acc);
        }
        v[e] = acc;
    }

    // 4-stage butterfly over bits 0..3: lane l ends with edge (l&15) summed
    // over its own 16-lane half; xor-16 combines the halves.
#pragma unroll
    for (int m = 8; m >= 1; m >>= 1) {
#pragma unroll
        for (int e = 0; e < m; e++) {
            float up   = (lane & m) ? v[e]     : v[e + m];
            float keep = (lane & m) ? v[e + m] : v[e];
            v[e] = keep + __shfl_xor_sync(FULL, up, m);
        }
    }
    v[0] += __shfl_xor_sync(FULL, v[0], 16);

    if (lane < 16 && base + lane < E) out[base + lane] = v[0] + b2;
}

// ---------------------------------------------------------------------------
extern "C" void kernel_launch(void* const* d_in, const int* in_sizes, int n_in,
                              void* d_out, int out_size) {
    const float* h    = (const float*)d_in[0];
    const int*   src  = (const int*)  d_in[1];
    const int*   dst  = (const int*)  d_in[2];
    const float* W1w  = (const float*)d_in[3];
    const float* W1b  = (const float*)d_in[4];
    const float* W2w  = (const float*)d_in[5];
    const float* W2b  = (const float*)d_in[6];
    float* out = (float*)d_out;

    const int E = in_sizes[1];   // 800000 edges

    // 1) fp16 conversions / weight repack
    size_t n8 = (size_t)N_NODES_PAD * N_FEAT / 8;
    split_h_kernel<<<(unsigned)((n8 + 255) / 256), 256>>>(h);
    size_t w4 = (size_t)N_OUT * N_FEAT / 4;
    split_w_kernel<<<(unsigned)((w4 + 255) / 256), 256>>>(W1w);

    // 2) Node projection GEMM (fp16, cp.async 3-stage)
    static int smem_set = 0;
    const int smem_bytes = 3 * BUF_H * 2;   // 3 stages * (A,B) bytes = 61440
    if (!smem_set) {
        cudaFuncSetAttribute(gemm_f16_kernel,
                             cudaFuncAttributeMaxDynamicSharedMemorySize, smem_bytes);
        smem_set = 1;
    }
    dim3 ggrid(N_OUT / 128, N_NODES_PAD / 128);
    gemm_f16_kernel<<<ggrid, 256, smem_bytes>>>(W1b);

    // 3) Per-edge gather + relu-dot: one warp per 16 edges
    int nwarps  = (E + 15) / 16;
    int eblocks = (nwarps + 7) / 8;
    edge_kernel<<<eblocks, 256>>>(src, dst, W2w, W2b, out, E);
}